// round 12
// baseline (speedup 1.0000x reference)
#include <cuda_runtime.h>
#include <cuda_bf16.h>
#include <cuda_fp16.h>
#include <cstdint>

#define B_ROWS 4096
#define D_DIM 1024
#define N2 8192
#define NTILE 64                 // 8192 / 128 tiles per side
#define NTILES_TRI (NTILE * (NTILE + 1) / 2)   // 2080
#define DP 512                   // row length in u16 (fp8 pairs)
#define KC16 64                  // u16 per K-chunk = 128 fp8 = 128 bytes/row
#define NCHUNK 8
#define DEPTH 3                  // pipeline stages (single-barrier multistage)
#define TILE_BYTES (128 * 128)   // XOR-swizzled 128B rows, no pad: 16 KB
#define STAGE_BYTES (2 * TILE_BYTES)                // A + B per stage: 32 KB
#define SMEM_TOTAL (DEPTH * STAGE_BYTES + 1024)     // 97.25 KB -> occ 2 @512thr

// rows pre-scaled by 64 -> acc = 4096 * sim ; exp(sim/0.5) = exp2(acc * SC)
#define EXP_SCALE (2.8853900817779268f / 4096.0f)
#define FP8_SCALE 64.0f

__device__ uint16_t g_reps[(size_t)N2 * DP];   // e4m3 pairs
__device__ float g_nom[N2];
__device__ float g_den[N2];

// ------------------------------ helpers -----------------------------------
__device__ __forceinline__ uint32_t smem_u32(const void* p) {
    return (uint32_t)__cvta_generic_to_shared(p);
}
__device__ __forceinline__ float fast_exp2(float x) {
    float y; asm("ex2.approx.f32 %0, %1;" : "=f"(y) : "f"(x)); return y;
}
__device__ __forceinline__ uint32_t sw128(uint32_t off) {
    return off ^ ((off >> 3) & 0x70);      // XOR row%8 into 16B-chunk bits
}
__device__ __forceinline__ void ldm_x4(uint32_t r[4], uint32_t saddr) {
    asm volatile("ldmatrix.sync.aligned.m8n8.x4.shared.b16 {%0,%1,%2,%3}, [%4];\n"
                 : "=r"(r[0]), "=r"(r[1]), "=r"(r[2]), "=r"(r[3])
                 : "r"(saddr));
}
// fp8 e4m3 MMA with fp16 accumulators: c/d = 2 regs (f16x2 pairs)
__device__ __forceinline__ void mma_fp8_h(uint32_t c[2], const uint32_t a[4],
                                          uint32_t b0, uint32_t b1) {
    asm volatile(
        "mma.sync.aligned.m16n8k32.row.col.f16.e4m3.e4m3.f16 "
        "{%0,%1}, {%2,%3,%4,%5}, {%6,%7}, {%0,%1};\n"
        : "+r"(c[0]), "+r"(c[1])
        : "r"(a[0]), "r"(a[1]), "r"(a[2]), "r"(a[3]), "r"(b0), "r"(b1));
}
__device__ __forceinline__ uint16_t cvt_e4m3x2(float hi, float lo) {
    uint16_t r;
    asm("cvt.rn.satfinite.e4m3x2.f32 %0, %1, %2;" : "=h"(r) : "f"(hi), "f"(lo));
    return r;
}
__device__ __forceinline__ void cp16(uint32_t s, const void* g) {
    asm volatile("cp.async.cg.shared.global [%0], [%1], 16;" :: "r"(s), "l"(g));
}
__device__ __forceinline__ void cp_commit() {
    asm volatile("cp.async.commit_group;" ::: "memory");
}
template <int N> __device__ __forceinline__ void cp_wait() {
    asm volatile("cp.async.wait_group %0;" :: "n"(N) : "memory");
}

// ---------------------------------------------------------------------------
// Kernel 1: L2-normalize rows -> fp8 e4m3 (x64) reps; zero accumulators.
// Warp-per-row, no __syncthreads (R11 version, near cvt floor).
// ---------------------------------------------------------------------------
__global__ void __launch_bounds__(256)
normalize_kernel(const float* __restrict__ emb_i,
                 const float* __restrict__ emb_j,
                 float* __restrict__ out) {
    const int t = threadIdx.x;
    const int warp = t >> 5, lane = t & 31;
    const int row = blockIdx.x * 8 + warp;

    if (lane == 0) { g_nom[row] = 0.0f; g_den[row] = 0.0f; }
    if (blockIdx.x == 0 && t == 0) out[0] = 0.0f;

    const float* src = (row < B_ROWS)
        ? emb_i + (size_t)row * D_DIM
        : emb_j + (size_t)(row - B_ROWS) * D_DIM;
    const float4* s4 = (const float4*)src;

    float4 v[8];
    #pragma unroll
    for (int i = 0; i < 8; i++)
        v[i] = s4[lane + 32 * i];                  // MLP 8, coalesced

    float ss = 0.0f;
    #pragma unroll
    for (int i = 0; i < 8; i++)
        ss += v[i].x*v[i].x + v[i].y*v[i].y + v[i].z*v[i].z + v[i].w*v[i].w;
    #pragma unroll
    for (int s = 16; s > 0; s >>= 1)
        ss += __shfl_xor_sync(0xffffffffu, ss, s);

    float scale = FP8_SCALE / fmaxf(sqrtf(ss), 1e-12f);

    uint32_t* d32 = (uint32_t*)(g_reps + (size_t)row * DP);
    #pragma unroll
    for (int i = 0; i < 8; i++) {
        uint16_t lo = cvt_e4m3x2(v[i].y * scale, v[i].x * scale);
        uint16_t hi = cvt_e4m3x2(v[i].w * scale, v[i].z * scale);
        d32[lane + 32 * i] = (uint32_t)lo | ((uint32_t)hi << 16);
    }
}

// ---------------------------------------------------------------------------
// Kernel 2: fused fp8 sim-GEMM (f16 accum) + exp + masked sums, triangle tiles.
// 512 threads / 16 warps, warp tile 32x32 -> 8 warps per SMSP at occ 2
// (occupancy experiment: is the legacy QMMA pipe rate-limited or warp-limited?)
// ---------------------------------------------------------------------------
__device__ __forceinline__ void load_tiles(uint32_t sA, uint32_t sB,
                                           const uint16_t* gA,
                                           const uint16_t* gB,
                                           int kc16, int tid) {
    #pragma unroll
    for (int i = 0; i < 2; i++) {
        int idx = tid + i * 512;           // 0..1023
        int r = idx >> 3, cb = idx & 7;    // 128 rows x 8 16B-chunks
        uint32_t sw = sw128(r * 128 + cb * 16);
        cp16(sA + sw, gA + (size_t)r * DP + kc16 + cb * 8);
        cp16(sB + sw, gB + (size_t)r * DP + kc16 + cb * 8);
    }
}

__global__ void __launch_bounds__(512, 2)
sim_kernel(const int* __restrict__ labels) {
    extern __shared__ char dsm[];
    uint32_t base = smem_u32(dsm);
    int* sLab = (int*)dsm;                       // 128 col labels
    uint32_t abase = base + 1024;                // stages

    int idx = blockIdx.x;
    int bm = 0;
    while (idx >= NTILE - bm) { idx -= NTILE - bm; bm++; }
    int bn = bm + idx;
    const bool diag = (bm == bn);

    const int rowbase = bm * 128, colbase = bn * 128;
    const int tid = threadIdx.x;
    const int warp = tid >> 5, lane = tid & 31;
    const int wm = warp >> 2;    // 0..3 -> m offset wm*32
    const int wn = warp & 3;     // 0..3 -> n offset wn*32

    if (tid < 128) sLab[tid] = labels[(colbase + tid) & (B_ROWS - 1)];

    uint32_t acc[2][4][2];                       // f16x2 accumulators (16 regs)
    #pragma unroll
    for (int mt = 0; mt < 2; mt++)
        #pragma unroll
        for (int nt = 0; nt < 4; nt++) { acc[mt][nt][0] = 0u; acc[mt][nt][1] = 0u; }

    const uint16_t* gA = g_reps + (size_t)rowbase * DP;
    const uint16_t* gB = g_reps + (size_t)colbase * DP;

    // prologue: chunks 0 and 1 into stages 0,1
    load_tiles(abase, abase + TILE_BYTES, gA, gB, 0, tid);
    cp_commit();
    load_tiles(abase + STAGE_BYTES, abase + STAGE_BYTES + TILE_BYTES, gA, gB, KC16, tid);
    cp_commit();

    #pragma unroll 1
    for (int c = 0; c < NCHUNK; c++) {
        int s = c % DEPTH;
        uint32_t stA = abase + s * STAGE_BYTES;
        uint32_t stB = stA + TILE_BYTES;

        cp_wait<1>();              // chunk c resident (chunk c+1 may be pending)
        __syncthreads();           // for all threads; also fences stage reuse

        #pragma unroll
        for (int ks = 0; ks < KC16; ks += 16) {      // 16 u16 = 32 fp8 per mma
            uint32_t afr[2][4];
            #pragma unroll
            for (int mt = 0; mt < 2; mt++) {
                int row = wm * 32 + mt * 16 + (lane & 15);
                int col = ks + (lane >> 4) * 8;
                ldm_x4(afr[mt], stA + sw128(row * 128 + col * 2));
            }
            uint32_t bfr[2][4];
            #pragma unroll
            for (int nb = 0; nb < 2; nb++) {
                int row = wn * 32 + nb * 16 + (lane & 15);
                int col = ks + (lane >> 4) * 8;
                ldm_x4(bfr[nb], stB + sw128(row * 128 + col * 2));
            }
            #pragma unroll
            for (int mt = 0; mt < 2; mt++)
                #pragma unroll
                for (int nt = 0; nt < 4; nt++)
                    mma_fp8_h(acc[mt][nt], afr[mt],
                              bfr[nt >> 1][nt & 1], bfr[nt >> 1][2 + (nt & 1)]);
        }

        // load chunk c+2 into stage (c+2)%3 — distinct from stages c, c+1;
        // the barrier above ordered all reads of its previous contents.
        int nc = c + 2;
        if (nc < NCHUNK) {
            int s2 = nc % DEPTH;
            uint32_t nA = abase + s2 * STAGE_BYTES;
            load_tiles(nA, nA + TILE_BYTES, gA, gB, nc * KC16, tid);
        }
        cp_commit();               // uniform commit count (empty groups in tail)
    }

    // ---------------- epilogue: exp + mask + row/col sums ----------------
    const int g = lane >> 2;
    const int q = lane & 3;

    int labR[4];
    #pragma unroll
    for (int ri = 0; ri < 4; ri++) {
        int R = rowbase + wm * 32 + (ri >> 1) * 16 + g + (ri & 1) * 8;
        labR[ri] = labels[R & (B_ROWS - 1)];
    }

    float dsum[4] = {0, 0, 0, 0};
    float nsum[4] = {0, 0, 0, 0};

    #pragma unroll
    for (int nt = 0; nt < 4; nt++) {
        int cloc = wn * 32 + nt * 8 + q * 2;
        int lab0 = sLab[cloc];
        int lab1 = sLab[cloc + 1];
        int C0 = colbase + cloc;
        float cse0 = 0.0f, cse1 = 0.0f, csn0 = 0.0f, csn1 = 0.0f;

        #pragma unroll
        for (int mt = 0; mt < 2; mt++) {
            #pragma unroll
            for (int half = 0; half < 2; half++) {   // which 8-row group
                int ri = mt * 2 + half;
                __half2 h2 = *(__half2*)&acc[mt][nt][half];
                float e0 = fast_exp2(__low2float(h2)  * EXP_SCALE);
                float e1 = fast_exp2(__high2float(h2) * EXP_SCALE);
                if (diag) {
                    int R = rowbase + wm * 32 + mt * 16 + g + half * 8;
                    if (R == C0)     e0 = 0.0f;
                    if (R == C0 + 1) e1 = 0.0f;
                }
                bool p0 = (lab0 == labR[ri]);
                bool p1 = (lab1 == labR[ri]);
                dsum[ri] += e0 + e1;
                nsum[ri] += (p0 ? e0 : 0.0f) + (p1 ? e1 : 0.0f);
                if (!diag) {
                    cse0 += e0; cse1 += e1;
                    csn0 += p0 ? e0 : 0.0f;
                    csn1 += p1 ? e1 : 0.0f;
                }
            }
        }

        if (!diag) {
            #pragma unroll
            for (int sh = 4; sh <= 16; sh <<= 1) {
                cse0 += __shfl_xor_sync(0xffffffffu, cse0, sh);
                cse1 += __shfl_xor_sync(0xffffffffu, cse1, sh);
                csn0 += __shfl_xor_sync(0xffffffffu, csn0, sh);
                csn1 += __shfl_xor_sync(0xffffffffu, csn1, sh);
            }
            if (g == 0) {
                atomicAdd(&g_den[C0],     cse0);
                atomicAdd(&g_den[C0 + 1], cse1);
                atomicAdd(&g_nom[C0],     csn0);
                atomicAdd(&g_nom[C0 + 1], csn1);
            }
        }
    }

    #pragma unroll
    for (int sh = 1; sh <= 2; sh <<= 1) {
        #pragma unroll
        for (int ri = 0; ri < 4; ri++) {
            dsum[ri] += __shfl_xor_sync(0xffffffffu, dsum[ri], sh);
            nsum[ri] += __shfl_xor_sync(0xffffffffu, nsum[ri], sh);
        }
    }
    if (q == 0) {
        #pragma unroll
        for (int ri = 0; ri < 4; ri++) {
            int R = rowbase + wm * 32 + (ri >> 1) * 16 + g + (ri & 1) * 8;
            atomicAdd(&g_den[R], dsum[ri]);
            atomicAdd(&g_nom[R], nsum[ri]);
        }
    }
}

// ---------------------------------------------------------------------------
// Kernel 3: loss = mean(log(den) - log(nom)); 8 blocks, atomic into out.
// ---------------------------------------------------------------------------
__global__ void __launch_bounds__(1024)
loss_kernel(float* __restrict__ out) {
    int i = blockIdx.x * blockDim.x + threadIdx.x;   // 8 x 1024 = 8192
    float s = logf(g_den[i]) - logf(g_nom[i]);
    #pragma unroll
    for (int sh = 16; sh > 0; sh >>= 1)
        s += __shfl_xor_sync(0xffffffffu, s, sh);
    __shared__ float red[32];
    int t = threadIdx.x;
    if ((t & 31) == 0) red[t >> 5] = s;
    __syncthreads();
    if (t < 32) {
        float v = red[t];
        #pragma unroll
        for (int sh = 16; sh > 0; sh >>= 1)
            v += __shfl_xor_sync(0xffffffffu, v, sh);
        if (t == 0) atomicAdd(out, v / (float)N2);
    }
}

// ---------------------------------------------------------------------------
extern "C" void kernel_launch(void* const* d_in, const int* in_sizes, int n_in,
                              void* d_out, int out_size) {
    const float* emb_i = (const float*)d_in[0];
    const float* emb_j = (const float*)d_in[1];
    const int* labels  = (const int*)d_in[2];
    float* out = (float*)d_out;

    cudaFuncSetAttribute(sim_kernel,
                         cudaFuncAttributeMaxDynamicSharedMemorySize, SMEM_TOTAL);

    normalize_kernel<<<N2 / 8, 256>>>(emb_i, emb_j, out);
    sim_kernel<<<NTILES_TRI, 512, SMEM_TOTAL>>>(labels);
    loss_kernel<<<8, 1024>>>(out);
}

// round 13
// speedup vs baseline: 1.0313x; 1.0313x over previous
#include <cuda_runtime.h>
#include <cuda_bf16.h>
#include <cuda_fp16.h>
#include <cstdint>

#define B_ROWS 4096
#define D_DIM 1024
#define N2 8192
#define NTILE 64                 // 8192 / 128 tiles per side
#define NTILES_TRI (NTILE * (NTILE + 1) / 2)   // 2080
#define DP 512                   // row length in u16 (fp8 pairs)
#define KC16 64                  // u16 per K-chunk = 128 fp8 = 128 bytes/row
#define NCHUNK 8
#define DEPTH 3                  // pipeline stages (single-barrier multistage)
#define TILE_BYTES (128 * 128)   // XOR-swizzled 128B rows, no pad: 16 KB
#define STAGE_BYTES (2 * TILE_BYTES)                // A + B per stage: 32 KB
#define SMEM_TOTAL (DEPTH * STAGE_BYTES + 1024)     // 97.25 KB -> occ 2

// rows pre-scaled by 64 -> acc = 4096 * sim ; exp(sim/0.5) = exp2(acc * SC)
#define EXP_SCALE (2.8853900817779268f / 4096.0f)
#define FP8_SCALE 64.0f

__device__ uint16_t g_reps[(size_t)N2 * DP];   // e4m3 pairs
__device__ float g_nom[N2];
__device__ float g_den[N2];

// ------------------------------ helpers -----------------------------------
__device__ __forceinline__ uint32_t smem_u32(const void* p) {
    return (uint32_t)__cvta_generic_to_shared(p);
}
__device__ __forceinline__ float fast_exp2(float x) {
    float y; asm("ex2.approx.f32 %0, %1;" : "=f"(y) : "f"(x)); return y;
}
__device__ __forceinline__ uint32_t sw128(uint32_t off) {
    return off ^ ((off >> 3) & 0x70);      // XOR row%8 into 16B-chunk bits
}
__device__ __forceinline__ void ldm_x4(uint32_t r[4], uint32_t saddr) {
    asm volatile("ldmatrix.sync.aligned.m8n8.x4.shared.b16 {%0,%1,%2,%3}, [%4];\n"
                 : "=r"(r[0]), "=r"(r[1]), "=r"(r[2]), "=r"(r[3])
                 : "r"(saddr));
}
// fp8 e4m3 MMA with fp16 accumulators: c/d = 2 regs (f16x2 pairs)
__device__ __forceinline__ void mma_fp8_h(uint32_t c[2], const uint32_t a[4],
                                          uint32_t b0, uint32_t b1) {
    asm volatile(
        "mma.sync.aligned.m16n8k32.row.col.f16.e4m3.e4m3.f16 "
        "{%0,%1}, {%2,%3,%4,%5}, {%6,%7}, {%0,%1};\n"
        : "+r"(c[0]), "+r"(c[1])
        : "r"(a[0]), "r"(a[1]), "r"(a[2]), "r"(a[3]), "r"(b0), "r"(b1));
}
__device__ __forceinline__ uint16_t cvt_e4m3x2(float hi, float lo) {
    uint16_t r;
    asm("cvt.rn.satfinite.e4m3x2.f32 %0, %1, %2;" : "=h"(r) : "f"(hi), "f"(lo));
    return r;
}
__device__ __forceinline__ void cp16(uint32_t s, const void* g) {
    asm volatile("cp.async.cg.shared.global [%0], [%1], 16;" :: "r"(s), "l"(g));
}
__device__ __forceinline__ void cp_commit() {
    asm volatile("cp.async.commit_group;" ::: "memory");
}
template <int N> __device__ __forceinline__ void cp_wait() {
    asm volatile("cp.async.wait_group %0;" :: "n"(N) : "memory");
}

// ---------------------------------------------------------------------------
// Kernel 1: L2-normalize rows -> fp8 e4m3 (x64) reps; zero accumulators.
// Warp-per-row, no __syncthreads (R11 version, near cvt floor).
// ---------------------------------------------------------------------------
__global__ void __launch_bounds__(256)
normalize_kernel(const float* __restrict__ emb_i,
                 const float* __restrict__ emb_j,
                 float* __restrict__ out) {
    const int t = threadIdx.x;
    const int warp = t >> 5, lane = t & 31;
    const int row = blockIdx.x * 8 + warp;

    if (lane == 0) { g_nom[row] = 0.0f; g_den[row] = 0.0f; }
    if (blockIdx.x == 0 && t == 0) out[0] = 0.0f;

    const float* src = (row < B_ROWS)
        ? emb_i + (size_t)row * D_DIM
        : emb_j + (size_t)(row - B_ROWS) * D_DIM;
    const float4* s4 = (const float4*)src;

    float4 v[8];
    #pragma unroll
    for (int i = 0; i < 8; i++)
        v[i] = s4[lane + 32 * i];                  // MLP 8, coalesced

    float ss = 0.0f;
    #pragma unroll
    for (int i = 0; i < 8; i++)
        ss += v[i].x*v[i].x + v[i].y*v[i].y + v[i].z*v[i].z + v[i].w*v[i].w;
    #pragma unroll
    for (int s = 16; s > 0; s >>= 1)
        ss += __shfl_xor_sync(0xffffffffu, ss, s);

    float scale = FP8_SCALE / fmaxf(sqrtf(ss), 1e-12f);

    uint32_t* d32 = (uint32_t*)(g_reps + (size_t)row * DP);
    #pragma unroll
    for (int i = 0; i < 8; i++) {
        uint16_t lo = cvt_e4m3x2(v[i].y * scale, v[i].x * scale);
        uint16_t hi = cvt_e4m3x2(v[i].w * scale, v[i].z * scale);
        d32[lane + 32 * i] = (uint32_t)lo | ((uint32_t)hi << 16);
    }
}

// ---------------------------------------------------------------------------
// Kernel 2: fused fp8 sim-GEMM (f16 accum) + exp + masked sums, triangle tiles.
// R11 config (8 warps, 32x64 warp tile, occ 2) — measured optimum.
// Loads for chunk c+2 issued right after the barrier (before MMAs): stage
// (c+2)%3 holds chunk c-1, fully consumed in iteration c-1 before the barrier.
// ---------------------------------------------------------------------------
__device__ __forceinline__ void load_tiles(uint32_t sA, uint32_t sB,
                                           const uint16_t* gA,
                                           const uint16_t* gB,
                                           int kc16, int tid) {
    #pragma unroll
    for (int i = 0; i < 4; i++) {
        int idx = tid + i * 256;           // 0..1023
        int r = idx >> 3, cb = idx & 7;    // 128 rows x 8 16B-chunks
        uint32_t sw = sw128(r * 128 + cb * 16);
        cp16(sA + sw, gA + (size_t)r * DP + kc16 + cb * 8);
        cp16(sB + sw, gB + (size_t)r * DP + kc16 + cb * 8);
    }
}

__global__ void __launch_bounds__(256, 2)
sim_kernel(const int* __restrict__ labels) {
    extern __shared__ char dsm[];
    uint32_t base = smem_u32(dsm);
    int* sLab = (int*)dsm;                       // 128 col labels
    uint32_t abase = base + 1024;                // stages

    int idx = blockIdx.x;
    int bm = 0;
    while (idx >= NTILE - bm) { idx -= NTILE - bm; bm++; }
    int bn = bm + idx;
    const bool diag = (bm == bn);

    const int rowbase = bm * 128, colbase = bn * 128;
    const int tid = threadIdx.x;
    const int warp = tid >> 5, lane = tid & 31;
    const int wm = warp >> 1;
    const int wn = warp & 1;

    if (tid < 128) sLab[tid] = labels[(colbase + tid) & (B_ROWS - 1)];

    uint32_t acc[2][8][2];                       // f16x2 accumulators
    #pragma unroll
    for (int mt = 0; mt < 2; mt++)
        #pragma unroll
        for (int nt = 0; nt < 8; nt++) { acc[mt][nt][0] = 0u; acc[mt][nt][1] = 0u; }

    const uint16_t* gA = g_reps + (size_t)rowbase * DP;
    const uint16_t* gB = g_reps + (size_t)colbase * DP;

    // prologue: chunks 0 and 1 into stages 0,1
    load_tiles(abase, abase + TILE_BYTES, gA, gB, 0, tid);
    cp_commit();
    load_tiles(abase + STAGE_BYTES, abase + STAGE_BYTES + TILE_BYTES, gA, gB, KC16, tid);
    cp_commit();

    #pragma unroll 1
    for (int c = 0; c < NCHUNK; c++) {
        int s = c % DEPTH;
        uint32_t stA = abase + s * STAGE_BYTES;
        uint32_t stB = stA + TILE_BYTES;

        cp_wait<1>();              // chunk c resident (chunk c+1 may be pending)
        __syncthreads();           // for all threads; also fences stage reuse

        // issue loads for chunk c+2 EARLY (stage (c+2)%3 = chunk c-1, consumed)
        int nc = c + 2;
        if (nc < NCHUNK) {
            int s2 = nc % DEPTH;
            uint32_t nA = abase + s2 * STAGE_BYTES;
            load_tiles(nA, nA + TILE_BYTES, gA, gB, nc * KC16, tid);
        }
        cp_commit();               // uniform commit count (empty groups in tail)

        #pragma unroll
        for (int ks = 0; ks < KC16; ks += 16) {      // 16 u16 = 32 fp8 per mma
            uint32_t afr[2][4];
            #pragma unroll
            for (int mt = 0; mt < 2; mt++) {
                int row = wm * 32 + mt * 16 + (lane & 15);
                int col = ks + (lane >> 4) * 8;
                ldm_x4(afr[mt], stA + sw128(row * 128 + col * 2));
            }
            uint32_t bfr[4][4];
            #pragma unroll
            for (int nb = 0; nb < 4; nb++) {
                int row = wn * 64 + nb * 16 + (lane & 15);
                int col = ks + (lane >> 4) * 8;
                ldm_x4(bfr[nb], stB + sw128(row * 128 + col * 2));
            }
            #pragma unroll
            for (int mt = 0; mt < 2; mt++)
                #pragma unroll
                for (int nt = 0; nt < 8; nt++)
                    mma_fp8_h(acc[mt][nt], afr[mt],
                              bfr[nt >> 1][nt & 1], bfr[nt >> 1][2 + (nt & 1)]);
        }
    }

    // ---------------- epilogue: exp + mask + row/col sums ----------------
    const int g = lane >> 2;
    const int q = lane & 3;

    int labR[4];
    #pragma unroll
    for (int ri = 0; ri < 4; ri++) {
        int R = rowbase + wm * 32 + (ri >> 1) * 16 + g + (ri & 1) * 8;
        labR[ri] = labels[R & (B_ROWS - 1)];
    }

    float dsum[4] = {0, 0, 0, 0};
    float nsum[4] = {0, 0, 0, 0};

    #pragma unroll
    for (int nt = 0; nt < 8; nt++) {
        int cloc = wn * 64 + nt * 8 + q * 2;
        int lab0 = sLab[cloc];
        int lab1 = sLab[cloc + 1];
        int C0 = colbase + cloc;
        float cse0 = 0.0f, cse1 = 0.0f, csn0 = 0.0f, csn1 = 0.0f;

        #pragma unroll
        for (int mt = 0; mt < 2; mt++) {
            #pragma unroll
            for (int half = 0; half < 2; half++) {   // which 8-row group
                int ri = mt * 2 + half;
                __half2 h2 = *(__half2*)&acc[mt][nt][half];
                float e0 = fast_exp2(__low2float(h2)  * EXP_SCALE);
                float e1 = fast_exp2(__high2float(h2) * EXP_SCALE);
                if (diag) {
                    int R = rowbase + wm * 32 + mt * 16 + g + half * 8;
                    if (R == C0)     e0 = 0.0f;
                    if (R == C0 + 1) e1 = 0.0f;
                }
                bool p0 = (lab0 == labR[ri]);
                bool p1 = (lab1 == labR[ri]);
                dsum[ri] += e0 + e1;
                nsum[ri] += (p0 ? e0 : 0.0f) + (p1 ? e1 : 0.0f);
                if (!diag) {
                    cse0 += e0; cse1 += e1;
                    csn0 += p0 ? e0 : 0.0f;
                    csn1 += p1 ? e1 : 0.0f;
                }
            }
        }

        if (!diag) {
            #pragma unroll
            for (int sh = 4; sh <= 16; sh <<= 1) {
                cse0 += __shfl_xor_sync(0xffffffffu, cse0, sh);
                cse1 += __shfl_xor_sync(0xffffffffu, cse1, sh);
                csn0 += __shfl_xor_sync(0xffffffffu, csn0, sh);
                csn1 += __shfl_xor_sync(0xffffffffu, csn1, sh);
            }
            if (g == 0) {
                atomicAdd(&g_den[C0],     cse0);
                atomicAdd(&g_den[C0 + 1], cse1);
                atomicAdd(&g_nom[C0],     csn0);
                atomicAdd(&g_nom[C0 + 1], csn1);
            }
        }
    }

    #pragma unroll
    for (int sh = 1; sh <= 2; sh <<= 1) {
        #pragma unroll
        for (int ri = 0; ri < 4; ri++) {
            dsum[ri] += __shfl_xor_sync(0xffffffffu, dsum[ri], sh);
            nsum[ri] += __shfl_xor_sync(0xffffffffu, nsum[ri], sh);
        }
    }
    if (q == 0) {
        #pragma unroll
        for (int ri = 0; ri < 4; ri++) {
            int R = rowbase + wm * 32 + (ri >> 1) * 16 + g + (ri & 1) * 8;
            atomicAdd(&g_den[R], dsum[ri]);
            atomicAdd(&g_nom[R], nsum[ri]);
        }
    }
}

// ---------------------------------------------------------------------------
// Kernel 3: loss = mean(log(den) - log(nom)); 8 blocks, atomic into out.
// ---------------------------------------------------------------------------
__global__ void __launch_bounds__(1024)
loss_kernel(float* __restrict__ out) {
    int i = blockIdx.x * blockDim.x + threadIdx.x;   // 8 x 1024 = 8192
    float s = __logf(g_den[i]) - __logf(g_nom[i]);
    #pragma unroll
    for (int sh = 16; sh > 0; sh >>= 1)
        s += __shfl_xor_sync(0xffffffffu, s, sh);
    __shared__ float red[32];
    int t = threadIdx.x;
    if ((t & 31) == 0) red[t >> 5] = s;
    __syncthreads();
    if (t < 32) {
        float v = red[t];
        #pragma unroll
        for (int sh = 16; sh > 0; sh >>= 1)
            v += __shfl_xor_sync(0xffffffffu, v, sh);
        if (t == 0) atomicAdd(out, v / (float)N2);
    }
}

// ---------------------------------------------------------------------------
extern "C" void kernel_launch(void* const* d_in, const int* in_sizes, int n_in,
                              void* d_out, int out_size) {
    const float* emb_i = (const float*)d_in[0];
    const float* emb_j = (const float*)d_in[1];
    const int* labels  = (const int*)d_in[2];
    float* out = (float*)d_out;

    cudaFuncSetAttribute(sim_kernel,
                         cudaFuncAttributeMaxDynamicSharedMemorySize, SMEM_TOTAL);

    normalize_kernel<<<N2 / 8, 256>>>(emb_i, emb_j, out);
    sim_kernel<<<NTILES_TRI, 256, SMEM_TOTAL>>>(labels);
    loss_kernel<<<8, 1024>>>(out);
}

// round 14
// speedup vs baseline: 1.0807x; 1.0479x over previous
#include <cuda_runtime.h>
#include <cuda_bf16.h>
#include <cuda_fp16.h>
#include <cstdint>

#define B_ROWS 4096
#define D_DIM 1024
#define N2 8192
#define NTILE 64                 // 8192 / 128 tiles per side
#define NTILES_TRI (NTILE * (NTILE + 1) / 2)   // 2080
#define DP 512                   // row length in u16 (fp8 pairs)
#define KC16 64                  // u16 per K-chunk = 128 fp8 = 128 bytes/row
#define NCHUNK 8
#define DEPTH 3                  // pipeline stages (single-barrier multistage)
#define TILE_BYTES (128 * 128)   // XOR-swizzled 128B rows, no pad: 16 KB
#define STAGE_BYTES (2 * TILE_BYTES)                // A + B per stage: 32 KB
#define SMEM_TOTAL (DEPTH * STAGE_BYTES + 1024)     // 97.25 KB -> occ 2

// rows pre-scaled by 64 -> acc = 4096 * sim ; exp(sim/0.5) = exp2(acc * SC)
#define EXP_SCALE (2.8853900817779268f / 4096.0f)
#define FP8_SCALE 64.0f

__device__ uint16_t g_reps[(size_t)N2 * DP];   // e4m3 pairs
__device__ float g_nom[N2];
__device__ float g_den[N2];

// ------------------------------ helpers -----------------------------------
__device__ __forceinline__ uint32_t smem_u32(const void* p) {
    return (uint32_t)__cvta_generic_to_shared(p);
}
__device__ __forceinline__ float fast_exp2(float x) {
    float y; asm("ex2.approx.f32 %0, %1;" : "=f"(y) : "f"(x)); return y;
}
__device__ __forceinline__ uint32_t sw128(uint32_t off) {
    return off ^ ((off >> 3) & 0x70);      // XOR row%8 into 16B-chunk bits
}
__device__ __forceinline__ void ldm_x4(uint32_t r[4], uint32_t saddr) {
    asm volatile("ldmatrix.sync.aligned.m8n8.x4.shared.b16 {%0,%1,%2,%3}, [%4];\n"
                 : "=r"(r[0]), "=r"(r[1]), "=r"(r[2]), "=r"(r[3])
                 : "r"(saddr));
}
// fp8 e4m3 MMA with fp16 accumulators: c/d = 2 regs (f16x2 pairs)
__device__ __forceinline__ void mma_fp8_h(uint32_t c[2], const uint32_t a[4],
                                          uint32_t b0, uint32_t b1) {
    asm volatile(
        "mma.sync.aligned.m16n8k32.row.col.f16.e4m3.e4m3.f16 "
        "{%0,%1}, {%2,%3,%4,%5}, {%6,%7}, {%0,%1};\n"
        : "+r"(c[0]), "+r"(c[1])
        : "r"(a[0]), "r"(a[1]), "r"(a[2]), "r"(a[3]), "r"(b0), "r"(b1));
}
__device__ __forceinline__ uint16_t cvt_e4m3x2(float hi, float lo) {
    uint16_t r;
    asm("cvt.rn.satfinite.e4m3x2.f32 %0, %1, %2;" : "=h"(r) : "f"(hi), "f"(lo));
    return r;
}
__device__ __forceinline__ void cp16(uint32_t s, const void* g) {
    asm volatile("cp.async.cg.shared.global [%0], [%1], 16;" :: "r"(s), "l"(g));
}
__device__ __forceinline__ void cp_commit() {
    asm volatile("cp.async.commit_group;" ::: "memory");
}
template <int N> __device__ __forceinline__ void cp_wait() {
    asm volatile("cp.async.wait_group %0;" :: "n"(N) : "memory");
}

// ---------------------------------------------------------------------------
// Kernel 1: L2-normalize rows -> fp8 e4m3 (x64) reps; zero accumulators.
// Warp-per-row, no __syncthreads; rsqrtf on the serial reduce->convert chain.
// ---------------------------------------------------------------------------
__global__ void __launch_bounds__(256)
normalize_kernel(const float* __restrict__ emb_i,
                 const float* __restrict__ emb_j,
                 float* __restrict__ out) {
    const int t = threadIdx.x;
    const int warp = t >> 5, lane = t & 31;
    const int row = blockIdx.x * 8 + warp;

    if (lane == 0) { g_nom[row] = 0.0f; g_den[row] = 0.0f; }
    if (blockIdx.x == 0 && t == 0) out[0] = 0.0f;

    const float* src = (row < B_ROWS)
        ? emb_i + (size_t)row * D_DIM
        : emb_j + (size_t)(row - B_ROWS) * D_DIM;
    const float4* s4 = (const float4*)src;

    float4 v[8];
    #pragma unroll
    for (int i = 0; i < 8; i++)
        v[i] = s4[lane + 32 * i];                  // MLP 8, coalesced

    float ss = 0.0f;
    #pragma unroll
    for (int i = 0; i < 8; i++)
        ss += v[i].x*v[i].x + v[i].y*v[i].y + v[i].z*v[i].z + v[i].w*v[i].w;
    #pragma unroll
    for (int s = 16; s > 0; s >>= 1)
        ss += __shfl_xor_sync(0xffffffffu, ss, s);

    float scale = FP8_SCALE * rsqrtf(fmaxf(ss, 1e-24f));

    uint32_t* d32 = (uint32_t*)(g_reps + (size_t)row * DP);
    #pragma unroll
    for (int i = 0; i < 8; i++) {
        uint16_t lo = cvt_e4m3x2(v[i].y * scale, v[i].x * scale);
        uint16_t hi = cvt_e4m3x2(v[i].w * scale, v[i].z * scale);
        d32[lane + 32 * i] = (uint32_t)lo | ((uint32_t)hi << 16);
    }
}

// ---------------------------------------------------------------------------
// Kernel 2: fused fp8 sim-GEMM (f16 accum) + exp + masked sums, triangle tiles.
// EXACT R11 configuration & ordering (measured optimum: 8 warps, 32x64 warp
// tile, occ 2, loads issued AFTER the MMA burst — R13 showed early loads hurt).
// ---------------------------------------------------------------------------
__device__ __forceinline__ void load_tiles(uint32_t sA, uint32_t sB,
                                           const uint16_t* gA,
                                           const uint16_t* gB,
                                           int kc16, int tid) {
    #pragma unroll
    for (int i = 0; i < 4; i++) {
        int idx = tid + i * 256;           // 0..1023
        int r = idx >> 3, cb = idx & 7;    // 128 rows x 8 16B-chunks
        uint32_t sw = sw128(r * 128 + cb * 16);
        cp16(sA + sw, gA + (size_t)r * DP + kc16 + cb * 8);
        cp16(sB + sw, gB + (size_t)r * DP + kc16 + cb * 8);
    }
}

__global__ void __launch_bounds__(256, 2)
sim_kernel(const int* __restrict__ labels) {
    extern __shared__ char dsm[];
    uint32_t base = smem_u32(dsm);
    int* sLab = (int*)dsm;                       // 128 col labels
    uint32_t abase = base + 1024;                // stages

    int idx = blockIdx.x;
    int bm = 0;
    while (idx >= NTILE - bm) { idx -= NTILE - bm; bm++; }
    int bn = bm + idx;
    const bool diag = (bm == bn);

    const int rowbase = bm * 128, colbase = bn * 128;
    const int tid = threadIdx.x;
    const int warp = tid >> 5, lane = tid & 31;
    const int wm = warp >> 1;
    const int wn = warp & 1;

    if (tid < 128) sLab[tid] = labels[(colbase + tid) & (B_ROWS - 1)];

    uint32_t acc[2][8][2];                       // f16x2 accumulators
    #pragma unroll
    for (int mt = 0; mt < 2; mt++)
        #pragma unroll
        for (int nt = 0; nt < 8; nt++) { acc[mt][nt][0] = 0u; acc[mt][nt][1] = 0u; }

    const uint16_t* gA = g_reps + (size_t)rowbase * DP;
    const uint16_t* gB = g_reps + (size_t)colbase * DP;

    // prologue: chunks 0 and 1 into stages 0,1
    load_tiles(abase, abase + TILE_BYTES, gA, gB, 0, tid);
    cp_commit();
    load_tiles(abase + STAGE_BYTES, abase + STAGE_BYTES + TILE_BYTES, gA, gB, KC16, tid);
    cp_commit();

    #pragma unroll 1
    for (int c = 0; c < NCHUNK; c++) {
        int s = c % DEPTH;
        uint32_t stA = abase + s * STAGE_BYTES;
        uint32_t stB = stA + TILE_BYTES;

        cp_wait<1>();              // chunk c resident (chunk c+1 may be pending)
        __syncthreads();           // for all threads; also fences stage reuse

        #pragma unroll
        for (int ks = 0; ks < KC16; ks += 16) {      // 16 u16 = 32 fp8 per mma
            uint32_t afr[2][4];
            #pragma unroll
            for (int mt = 0; mt < 2; mt++) {
                int row = wm * 32 + mt * 16 + (lane & 15);
                int col = ks + (lane >> 4) * 8;
                ldm_x4(afr[mt], stA + sw128(row * 128 + col * 2));
            }
            uint32_t bfr[4][4];
            #pragma unroll
            for (int nb = 0; nb < 4; nb++) {
                int row = wn * 64 + nb * 16 + (lane & 15);
                int col = ks + (lane >> 4) * 8;
                ldm_x4(bfr[nb], stB + sw128(row * 128 + col * 2));
            }
            #pragma unroll
            for (int mt = 0; mt < 2; mt++)
                #pragma unroll
                for (int nt = 0; nt < 8; nt++)
                    mma_fp8_h(acc[mt][nt], afr[mt],
                              bfr[nt >> 1][nt & 1], bfr[nt >> 1][2 + (nt & 1)]);
        }

        // load chunk c+2 into stage (c+2)%3 — distinct from stages c, c+1;
        // the barrier above ordered all reads of its previous contents.
        int nc = c + 2;
        if (nc < NCHUNK) {
            int s2 = nc % DEPTH;
            uint32_t nA = abase + s2 * STAGE_BYTES;
            load_tiles(nA, nA + TILE_BYTES, gA, gB, nc * KC16, tid);
        }
        cp_commit();               // uniform commit count (empty groups in tail)
    }

    // ---------------- epilogue: exp + mask + row/col sums ----------------
    const int g = lane >> 2;
    const int q = lane & 3;

    int labR[4];
    #pragma unroll
    for (int ri = 0; ri < 4; ri++) {
        int R = rowbase + wm * 32 + (ri >> 1) * 16 + g + (ri & 1) * 8;
        labR[ri] = labels[R & (B_ROWS - 1)];
    }

    float dsum[4] = {0, 0, 0, 0};
    float nsum[4] = {0, 0, 0, 0};

    #pragma unroll
    for (int nt = 0; nt < 8; nt++) {
        int cloc = wn * 64 + nt * 8 + q * 2;
        int lab0 = sLab[cloc];
        int lab1 = sLab[cloc + 1];
        int C0 = colbase + cloc;
        float cse0 = 0.0f, cse1 = 0.0f, csn0 = 0.0f, csn1 = 0.0f;

        #pragma unroll
        for (int mt = 0; mt < 2; mt++) {
            #pragma unroll
            for (int half = 0; half < 2; half++) {   // which 8-row group
                int ri = mt * 2 + half;
                __half2 h2 = *(__half2*)&acc[mt][nt][half];
                float e0 = fast_exp2(__low2float(h2)  * EXP_SCALE);
                float e1 = fast_exp2(__high2float(h2) * EXP_SCALE);
                if (diag) {
                    int R = rowbase + wm * 32 + mt * 16 + g + half * 8;
                    if (R == C0)     e0 = 0.0f;
                    if (R == C0 + 1) e1 = 0.0f;
                }
                bool p0 = (lab0 == labR[ri]);
                bool p1 = (lab1 == labR[ri]);
                dsum[ri] += e0 + e1;
                nsum[ri] += (p0 ? e0 : 0.0f) + (p1 ? e1 : 0.0f);
                if (!diag) {
                    cse0 += e0; cse1 += e1;
                    csn0 += p0 ? e0 : 0.0f;
                    csn1 += p1 ? e1 : 0.0f;
                }
            }
        }

        if (!diag) {
            #pragma unroll
            for (int sh = 4; sh <= 16; sh <<= 1) {
                cse0 += __shfl_xor_sync(0xffffffffu, cse0, sh);
                cse1 += __shfl_xor_sync(0xffffffffu, cse1, sh);
                csn0 += __shfl_xor_sync(0xffffffffu, csn0, sh);
                csn1 += __shfl_xor_sync(0xffffffffu, csn1, sh);
            }
            if (g == 0) {
                atomicAdd(&g_den[C0],     cse0);
                atomicAdd(&g_den[C0 + 1], cse1);
                atomicAdd(&g_nom[C0],     csn0);
                atomicAdd(&g_nom[C0 + 1], csn1);
            }
        }
    }

    #pragma unroll
    for (int sh = 1; sh <= 2; sh <<= 1) {
        #pragma unroll
        for (int ri = 0; ri < 4; ri++) {
            dsum[ri] += __shfl_xor_sync(0xffffffffu, dsum[ri], sh);
            nsum[ri] += __shfl_xor_sync(0xffffffffu, nsum[ri], sh);
        }
    }
    if (q == 0) {
        #pragma unroll
        for (int ri = 0; ri < 4; ri++) {
            int R = rowbase + wm * 32 + (ri >> 1) * 16 + g + (ri & 1) * 8;
            atomicAdd(&g_den[R], dsum[ri]);
            atomicAdd(&g_nom[R], nsum[ri]);
        }
    }
}

// ---------------------------------------------------------------------------
// Kernel 3: loss = mean(log(den) - log(nom)); 8 blocks, atomic into out.
// ---------------------------------------------------------------------------
__global__ void __launch_bounds__(1024)
loss_kernel(float* __restrict__ out) {
    int i = blockIdx.x * blockDim.x + threadIdx.x;   // 8 x 1024 = 8192
    float s = __logf(g_den[i]) - __logf(g_nom[i]);
    #pragma unroll
    for (int sh = 16; sh > 0; sh >>= 1)
        s += __shfl_xor_sync(0xffffffffu, s, sh);
    __shared__ float red[32];
    int t = threadIdx.x;
    if ((t & 31) == 0) red[t >> 5] = s;
    __syncthreads();
    if (t < 32) {
        float v = red[t];
        #pragma unroll
        for (int sh = 16; sh > 0; sh >>= 1)
            v += __shfl_xor_sync(0xffffffffu, v, sh);
        if (t == 0) atomicAdd(out, v / (float)N2);
    }
}

// ---------------------------------------------------------------------------
extern "C" void kernel_launch(void* const* d_in, const int* in_sizes, int n_in,
                              void* d_out, int out_size) {
    const float* emb_i = (const float*)d_in[0];
    const float* emb_j = (const float*)d_in[1];
    const int* labels  = (const int*)d_in[2];
    float* out = (float*)d_out;

    cudaFuncSetAttribute(sim_kernel,
                         cudaFuncAttributeMaxDynamicSharedMemorySize, SMEM_TOTAL);

    normalize_kernel<<<N2 / 8, 256>>>(emb_i, emb_j, out);
    sim_kernel<<<NTILES_TRI, 256, SMEM_TOTAL>>>(labels);
    loss_kernel<<<8, 1024>>>(out);
}